// round 12
// baseline (speedup 1.0000x reference)
#include <cuda_runtime.h>
#include <cuda_bf16.h>
#include <cstdint>
#include <math.h>

#define CDIM 256
#define BMAX 8
#define NSPLIT 32
#define MSIZE (CDIM*CDIM)

// ---------------- device scratch (no allocations allowed) ----------------
__device__ float g_mean_t[CDIM];
__device__ float g_mean_x[BMAX*CDIM];
__device__ float g_part[NSPLIT*BMAX*MSIZE];     // 64 MB split-K partials
__device__ float g_rowsum[NSPLIT*BMAX*CDIM];
__device__ float g_cov_t[MSIZE];
__device__ float g_cov_x[BMAX*MSIZE];
__device__ float g_S[MSIZE];                     // cov_t_sqrt
__device__ float g_tmpM[BMAX*MSIZE];
__device__ float g_M[BMAX*MSIZE];
__device__ float g_y0[BMAX*MSIZE];
__device__ float g_y1[BMAX*MSIZE];
__device__ float g_z0[BMAX*MSIZE];
__device__ float g_z1[BMAX*MSIZE];
__device__ float g_t[BMAX*MSIZE];
__device__ float g_norm_t[1];
__device__ float g_norm_b[BMAX];

// grid barrier state (even number of flips per launch -> returns to {0,0})
__device__ unsigned g_barcnt = 0;
__device__ unsigned g_barflag = 0;

// ================= mma helpers (baseline PTX only) =================
__device__ __forceinline__ void mma_bf16(float* d, const uint32_t* a, const uint32_t* b) {
    asm volatile("mma.sync.aligned.m16n8k16.row.col.f32.bf16.bf16.f32 "
        "{%0,%1,%2,%3}, {%4,%5,%6,%7}, {%8,%9}, {%0,%1,%2,%3};"
        : "+f"(d[0]), "+f"(d[1]), "+f"(d[2]), "+f"(d[3])
        : "r"(a[0]), "r"(a[1]), "r"(a[2]), "r"(a[3]), "r"(b[0]), "r"(b[1]));
}
__device__ __forceinline__ void ldsm_x4(uint32_t addr, uint32_t* r) {
    asm volatile("ldmatrix.sync.aligned.m8n8.x4.shared.b16 {%0,%1,%2,%3}, [%4];"
        : "=r"(r[0]), "=r"(r[1]), "=r"(r[2]), "=r"(r[3]) : "r"(addr));
}
__device__ __forceinline__ void ldsm_x2(uint32_t addr, uint32_t* r) {
    asm volatile("ldmatrix.sync.aligned.m8n8.x2.shared.b16 {%0,%1}, [%2];"
        : "=r"(r[0]), "=r"(r[1]) : "r"(addr));
}
__device__ __forceinline__ uint32_t smem_to_u32(const void* smem_ptr) {
    uint32_t addr;
    asm("{ .reg .u64 tmp; cvta.to.shared.u64 tmp, %1; cvt.u32.u64 %0, tmp; }"
        : "=r"(addr) : "l"(smem_ptr));
    return addr;
}
__device__ __forceinline__ uint32_t bits2(__nv_bfloat162 v) {
    return *reinterpret_cast<uint32_t*>(&v);
}

// ================= bf16x3 mma.sync SYRK (R4-validated) + fused row sums ======
#define SYRK_STAGE_BYTES 40960
#define SYRK_SMEM_BYTES  81920

__global__ void __launch_bounds__(256) syrk_mma_kernel(const float* __restrict__ X,
                                                       float* __restrict__ part,
                                                       int K, int klen, int nb)
{
    extern __shared__ char smem[];
    const int t    = threadIdx.x;
    const int lane = t & 31;
    const int wid  = t >> 5;
    const int warp_m = wid & 3;
    const int warp_n = wid >> 2;

    const int t3 = blockIdx.x;
    const int ti = (t3 == 2) ? 1 : 0;
    const int tj = (t3 == 0) ? 0 : 1;
    const bool diag = (ti == tj);
    const int b  = blockIdx.y;
    const int sp = blockIdx.z;

    const uint32_t sbase = smem_to_u32(smem);

    const size_t baseA = (size_t)b * CDIM * K + (size_t)(ti * 128) * K + (size_t)sp * klen;
    const size_t baseB = (size_t)b * CDIM * K + (size_t)(tj * 128) * K + (size_t)sp * klen;
    const int lrow = t >> 3;
    const int lc4  = t & 7;
    const float* gA = X + baseA + (size_t)lrow * K + lc4 * 4;
    const float* gB = X + baseB + (size_t)lrow * K + lc4 * 4;

    const int a_lr = lane & 7, a_lg = lane >> 3;
    const uint32_t a_off = (uint32_t)((a_lr + (a_lg & 1) * 8) * 80 + ((a_lg >> 1) * 8) * 2);
    const uint32_t b_off = (uint32_t)((lane & 7) * 80 + (((lane >> 3) & 1) * 8) * 2);

    float acc[2][8][4] = {};
    float rs[4] = {0.f, 0.f, 0.f, 0.f};
    float4 pa[4], pb[4];
    const int S = klen >> 5;

    #pragma unroll
    for (int it = 0; it < 4; it++) pa[it] = *(const float4*)(gA + (size_t)(it * 32) * K);
    if (!diag) {
        #pragma unroll
        for (int it = 0; it < 4; it++) pb[it] = *(const float4*)(gB + (size_t)(it * 32) * K);
    }

    for (int s = 0; s < S; s++) {
        const uint32_t bufo = (uint32_t)((s & 1) * SYRK_STAGE_BYTES);
        char* bufc = smem + bufo;

        #pragma unroll
        for (int it = 0; it < 4; it++) {
            float4 v = pa[it];
            if (diag) rs[it] += (v.x + v.y) + (v.z + v.w);
            __nv_bfloat162 h01 = __floats2bfloat162_rn(v.x, v.y);
            __nv_bfloat162 h23 = __floats2bfloat162_rn(v.z, v.w);
            float l0 = v.x - __low2float(h01);
            float l1 = v.y - __high2float(h01);
            float l2 = v.z - __low2float(h23);
            float l3 = v.w - __high2float(h23);
            __nv_bfloat162 lo01 = __floats2bfloat162_rn(l0, l1);
            __nv_bfloat162 lo23 = __floats2bfloat162_rn(l2, l3);
            uint32_t off = (uint32_t)((lrow + it * 32) * 80 + lc4 * 8);
            *(uint2*)(bufc + off)         = make_uint2(bits2(h01), bits2(h23));
            *(uint2*)(bufc + 10240 + off) = make_uint2(bits2(lo01), bits2(lo23));
        }
        if (!diag) {
            #pragma unroll
            for (int it = 0; it < 4; it++) {
                float4 v = pb[it];
                __nv_bfloat162 h01 = __floats2bfloat162_rn(v.x, v.y);
                __nv_bfloat162 h23 = __floats2bfloat162_rn(v.z, v.w);
                float l0 = v.x - __low2float(h01);
                float l1 = v.y - __high2float(h01);
                float l2 = v.z - __low2float(h23);
                float l3 = v.w - __high2float(h23);
                __nv_bfloat162 lo01 = __floats2bfloat162_rn(l0, l1);
                __nv_bfloat162 lo23 = __floats2bfloat162_rn(l2, l3);
                uint32_t off = (uint32_t)((lrow + it * 32) * 80 + lc4 * 8);
                *(uint2*)(bufc + 20480 + off) = make_uint2(bits2(h01), bits2(h23));
                *(uint2*)(bufc + 30720 + off) = make_uint2(bits2(lo01), bits2(lo23));
            }
        }
        __syncthreads();

        if (s + 1 < S) {
            const float* nA = gA + (s + 1) * 32;
            #pragma unroll
            for (int it = 0; it < 4; it++) pa[it] = *(const float4*)(nA + (size_t)(it * 32) * K);
            if (!diag) {
                const float* nB = gB + (s + 1) * 32;
                #pragma unroll
                for (int it = 0; it < 4; it++) pb[it] = *(const float4*)(nB + (size_t)(it * 32) * K);
            }
        }

        const uint32_t ah_base = sbase + bufo;
        const uint32_t al_base = ah_base + 10240;
        const uint32_t bh_base = diag ? ah_base : ah_base + 20480;
        const uint32_t bl_base = diag ? al_base : ah_base + 30720;
        #pragma unroll
        for (int kf = 0; kf < 2; kf++) {
            const uint32_t koff = (uint32_t)(kf * 32);
            uint32_t ah[2][4], al[2][4];
            #pragma unroll
            for (int m = 0; m < 2; m++) {
                uint32_t ro = (uint32_t)((warp_m * 32 + m * 16) * 80) + a_off + koff;
                ldsm_x4(ah_base + ro, ah[m]);
                ldsm_x4(al_base + ro, al[m]);
            }
            #pragma unroll
            for (int n = 0; n < 8; n++) {
                uint32_t ro = (uint32_t)((warp_n * 64 + n * 8) * 80) + b_off + koff;
                uint32_t bh[2], bl[2];
                ldsm_x2(bh_base + ro, bh);
                ldsm_x2(bl_base + ro, bl);
                #pragma unroll
                for (int m = 0; m < 2; m++) {
                    mma_bf16(acc[m][n], ah[m], bh);
                    mma_bf16(acc[m][n], ah[m], bl);
                    mma_bf16(acc[m][n], al[m], bh);
                }
            }
        }
        __syncthreads();
    }

    // fused row sums (diag tiles cover every row exactly once)
    if (diag) {
        #pragma unroll
        for (int it = 0; it < 4; it++) {
            float r = rs[it];
            r += __shfl_xor_sync(0xffffffffu, r, 1);
            r += __shfl_xor_sync(0xffffffffu, r, 2);
            r += __shfl_xor_sync(0xffffffffu, r, 4);
            if ((t & 7) == 0) {
                int row = ti * 128 + lrow + it * 32;
                g_rowsum[((size_t)sp * nb + b) * CDIM + row] = r;
            }
        }
    }

    float* osm = (float*)smem;
    {
        int r0 = warp_m * 32 + (lane >> 2);
        int c0 = warp_n * 64 + (lane & 3) * 2;
        #pragma unroll
        for (int m = 0; m < 2; m++) {
            #pragma unroll
            for (int n = 0; n < 8; n++) {
                int rr = r0 + m * 16;
                int cc = c0 + n * 8;
                osm[rr * 128 + cc]           = acc[m][n][0];
                osm[rr * 128 + cc + 1]       = acc[m][n][1];
                osm[(rr + 8) * 128 + cc]     = acc[m][n][2];
                osm[(rr + 8) * 128 + cc + 1] = acc[m][n][3];
            }
        }
    }
    __syncthreads();
    {
        float* out = part + ((size_t)sp * nb + b) * MSIZE
                     + (size_t)(ti * 128) * CDIM + tj * 128;
        #pragma unroll
        for (int it = 0; it < 16; it++) {
            int idx = it * 256 + t;
            int row = idx >> 5;
            int c4  = idx & 31;
            *(float4*)(out + (size_t)row * CDIM + c4 * 4) =
                *(float4*)(osm + row * 128 + c4 * 4);
        }
    }
}

// ---------------- mean from rowsum partials ----------------
__global__ void mean_from_rowsum(float* __restrict__ mean, int nb, float inv_len)
{
    int b = blockIdx.x;
    int c = threadIdx.x;
    float s = 0.f;
    #pragma unroll 8
    for (int sp = 0; sp < NSPLIT; sp++)
        s += g_rowsum[((size_t)sp * nb + b) * CDIM + c];
    mean[b * CDIM + c] = s * inv_len;
}

// ---------------- cov epilogue ----------------
__global__ void cov_epilogue_kernel(const float* __restrict__ part, int nb,
                                    const float* __restrict__ mean,
                                    float* __restrict__ cov, float inv_n)
{
    int i = blockIdx.x;
    int b = blockIdx.y;
    int j = threadIdx.x;
    int ii = min(i, j), jj = max(i, j);
    float s = 0.f;
    #pragma unroll 8
    for (int sp = 0; sp < NSPLIT; sp++)
        s += part[((size_t)sp * nb + b) * MSIZE + ii * CDIM + jj];
    float v = s * inv_n - mean[b * CDIM + i] * mean[b * CDIM + j] + ((i == j) ? 1e-4f : 0.f);
    cov[(size_t)b * MSIZE + i * CDIM + j] = v;
}

// ---------------- Frobenius norm per matrix ----------------
__global__ void frob_kernel(const float* __restrict__ A, float* __restrict__ norm)
{
    __shared__ float sm[256];
    const float4* p = (const float4*)(A + (size_t)blockIdx.x * MSIZE);
    float s = 0.f;
    for (int i = threadIdx.x; i < MSIZE / 4; i += 256) {
        float4 v = p[i];
        s += v.x * v.x + v.y * v.y + v.z * v.z + v.w * v.w;
    }
    sm[threadIdx.x] = s;
    __syncthreads();
    for (int off = 128; off > 0; off >>= 1) {
        if (threadIdx.x < off) sm[threadIdx.x] += sm[threadIdx.x + off];
        __syncthreads();
    }
    if (threadIdx.x == 0) norm[blockIdx.x] = sqrtf(sm[0]);
}

// ---------------- NS init: y = A/norm, z = I (fp32) ----------------
__global__ void ns_init_kernel(const float* __restrict__ A, const float* __restrict__ norm,
                               float* __restrict__ y, float* __restrict__ z)
{
    int b = blockIdx.x;
    int i4 = blockIdx.y * 256 + threadIdx.x;
    float inv = 1.f / norm[b];
    size_t off = (size_t)b * MSIZE + (size_t)i4 * 4;
    float4 v = *(const float4*)(A + off);
    v.x *= inv; v.y *= inv; v.z *= inv; v.w *= inv;
    *(float4*)(y + off) = v;
    int e = i4 * 4;
    int row = e >> 8;
    int c0 = e & 255;
    float4 zi;
    zi.x = (row == c0    ) ? 1.f : 0.f;
    zi.y = (row == c0 + 1) ? 1.f : 0.f;
    zi.z = (row == c0 + 2) ? 1.f : 0.f;
    zi.w = (row == c0 + 3) ? 1.f : 0.f;
    *(float4*)(z + off) = zi;
}

// ============ fp32 FFMA 64x64 tile engine (R4 mm256 math, callable) ==========
__device__ __forceinline__ void ffma_tile(
    const float* __restrict__ A, const float* __restrict__ B, float* __restrict__ C,
    int ti, int tj, float alpha, float beta,
    float (*As)[68], float (*Bs)[68])
{
    const int t  = threadIdx.x;
    const int lr = t >> 2;
    const int lk = (t & 3) * 4;
    const int br = t >> 4;
    const int bc = (t & 15) * 4;
    const int ty = t >> 4;
    const int tx = t & 15;

    float acc[4][4] = {};

    for (int k0 = 0; k0 < CDIM; k0 += 16) {
        float4 va = *(const float4*)(A + (size_t)(ti * 64 + lr) * CDIM + k0 + lk);
        float4 vb = *(const float4*)(B + (size_t)(k0 + br) * CDIM + tj * 64 + bc);
        __syncthreads();
        As[lk+0][lr] = va.x; As[lk+1][lr] = va.y; As[lk+2][lr] = va.z; As[lk+3][lr] = va.w;
        *(float4*)&Bs[br][bc] = vb;
        __syncthreads();
        #pragma unroll
        for (int k = 0; k < 16; k++) {
            float4 a4 = *(const float4*)&As[k][ty * 4];
            float4 b4 = *(const float4*)&Bs[k][tx * 4];
            acc[0][0] += a4.x * b4.x; acc[0][1] += a4.x * b4.y; acc[0][2] += a4.x * b4.z; acc[0][3] += a4.x * b4.w;
            acc[1][0] += a4.y * b4.x; acc[1][1] += a4.y * b4.y; acc[1][2] += a4.y * b4.z; acc[1][3] += a4.y * b4.w;
            acc[2][0] += a4.z * b4.x; acc[2][1] += a4.z * b4.y; acc[2][2] += a4.z * b4.z; acc[2][3] += a4.z * b4.w;
            acc[3][0] += a4.w * b4.x; acc[3][1] += a4.w * b4.y; acc[3][2] += a4.w * b4.z; acc[3][3] += a4.w * b4.w;
        }
    }

    #pragma unroll
    for (int i = 0; i < 4; i++) {
        int gi = ti * 64 + ty * 4 + i;
        #pragma unroll
        for (int j = 0; j < 4; j++) {
            int gj = tj * 64 + tx * 4 + j;
            C[gi * CDIM + gj] = alpha * acc[i][j] + ((gi == gj) ? beta : 0.f);
        }
    }
}

// ---------------- standalone mm256 (sandwich): C = alpha*A@B + beta*I --------
__global__ void __launch_bounds__(256) mm256_kernel(
    const float* __restrict__ A, int sA, const float* __restrict__ B, int sB,
    float* __restrict__ C, float alpha, float beta)
{
    __shared__ float As[16][68];
    __shared__ float Bs[16][68];
    const int item = blockIdx.y;
    ffma_tile(A + (size_t)sA * item, B + (size_t)sB * item, C + (size_t)item * MSIZE,
              blockIdx.x >> 2, blockIdx.x & 3, alpha, beta, As, Bs);
}

// ================= persistent fp32 FFMA NS chain =================
__device__ __forceinline__ void grid_barrier(unsigned* sense, unsigned G)
{
    __threadfence();
    __syncthreads();
    if (threadIdx.x == 0) {
        unsigned s = *sense ^ 1u;
        *sense = s;
        unsigned old = atomicAdd(&g_barcnt, 1u);
        if (old == G - 1u) {
            g_barcnt = 0u;
            __threadfence();
            atomicExch(&g_barflag, s);
        } else {
            while (atomicAdd(&g_barflag, 0u) != s) __nanosleep(64);
            __threadfence();
        }
    }
    __syncthreads();
}

__global__ void __launch_bounds__(256) ns_chain_ffma(int nb)
{
    __shared__ float As[16][68];
    __shared__ float Bs[16][68];
    const unsigned G = gridDim.x;
    unsigned sense = 0;
    int cur = 0;
    float* ybuf[2] = {g_y0, g_y1};
    float* zbuf[2] = {g_z0, g_z1};

    for (int iter = 0; iter < 12; iter++) {
        // stage1: t = 1.5 I - 0.5 (z @ y)
        const int nj1 = nb * 16;
        for (int job = blockIdx.x; job < nj1; job += (int)G) {
            int b = job >> 4, tile = job & 15;
            size_t mo = (size_t)b * MSIZE;
            ffma_tile(zbuf[cur] + mo, ybuf[cur] + mo, g_t + mo,
                      tile >> 2, tile & 3, -0.5f, 1.5f, As, Bs);
        }
        grid_barrier(&sense, G);

        // stage2: y' = y @ t ; z' = t @ z
        const int nj2 = nb * 32;
        for (int job = blockIdx.x; job < nj2; job += (int)G) {
            bool zpath = (job >= nj1);
            int jj = zpath ? job - nj1 : job;
            int b = jj >> 4, tile = jj & 15;
            size_t mo = (size_t)b * MSIZE;
            if (!zpath)
                ffma_tile(ybuf[cur] + mo, g_t + mo, ybuf[cur ^ 1] + mo,
                          tile >> 2, tile & 3, 1.f, 0.f, As, Bs);
            else
                ffma_tile(g_t + mo, zbuf[cur] + mo, zbuf[cur ^ 1] + mo,
                          tile >> 2, tile & 3, 1.f, 0.f, As, Bs);
        }
        grid_barrier(&sense, G);
        cur ^= 1;
    }
    // 12 iterations: final y lands in g_y0
}

// ---------------- S = y * sqrt(norm_t) ----------------
__global__ void scale_kernel(const float* __restrict__ y, const float* __restrict__ norm,
                             float* __restrict__ out)
{
    float sc = sqrtf(norm[0]);
    int i = blockIdx.x * 256 + threadIdx.x;
    out[i] = y[i] * sc;
}

// ---------------- final: mean_diff + cov_diff ----------------
__global__ void final_kernel(const float* __restrict__ mean_x, const float* __restrict__ mean_t,
                             const float* __restrict__ cov_t, const float* __restrict__ cov_x,
                             const float* __restrict__ yb, const float* __restrict__ normb,
                             int B, float* __restrict__ out)
{
    __shared__ float sm[256];
    float s = 0.f;
    int n = B * CDIM;
    for (int idx = threadIdx.x; idx < n; idx += 256) {
        int b = idx >> 8;
        int c = idx & 255;
        float d = mean_x[idx] - mean_t[c];
        float st = sqrtf(normb[b]) * yb[(size_t)b * MSIZE + c * (CDIM + 1)];
        s += d * d + cov_t[c * (CDIM + 1)] + cov_x[(size_t)b * MSIZE + c * (CDIM + 1)] - 2.f * st;
    }
    sm[threadIdx.x] = s;
    __syncthreads();
    for (int off = 128; off > 0; off >>= 1) {
        if (threadIdx.x < off) sm[threadIdx.x] += sm[threadIdx.x + off];
        __syncthreads();
    }
    if (threadIdx.x == 0) out[0] = sm[0] / (float)n;
}

// ---------------- host orchestration ----------------
template <typename T>
static float* sym_addr(const T& symbol)
{
    void* p = nullptr;
    cudaGetSymbolAddress(&p, symbol);
    return (float*)p;
}

extern "C" void kernel_launch(void* const* d_in, const int* in_sizes, int n_in,
                              void* d_out, int out_size)
{
    const float* x  = (const float*)d_in[0];
    const float* tf = (const float*)d_in[1];
    const int HW = 65536;
    int B  = in_sizes[0] / (CDIM * HW);         // 8
    int NT = in_sizes[1] / CDIM;                // 16384

    float* p_mean_t = sym_addr(g_mean_t);
    float* p_mean_x = sym_addr(g_mean_x);
    float* p_part   = sym_addr(g_part);
    float* p_cov_t  = sym_addr(g_cov_t);
    float* p_cov_x  = sym_addr(g_cov_x);
    float* p_S      = sym_addr(g_S);
    float* p_tmpM   = sym_addr(g_tmpM);
    float* p_M      = sym_addr(g_M);
    float* p_y0     = sym_addr(g_y0);
    float* p_z0     = sym_addr(g_z0);
    float* p_norm_t = sym_addr(g_norm_t);
    float* p_norm_b = sym_addr(g_norm_b);

    cudaFuncSetAttribute(syrk_mma_kernel, cudaFuncAttributeMaxDynamicSharedMemorySize,
                         SYRK_SMEM_BYTES);

    // ---- target branch: cov_t and its NS sqrt ----
    syrk_mma_kernel<<<dim3(3, 1, NSPLIT), 256, SYRK_SMEM_BYTES>>>(tf, p_part, NT, NT / NSPLIT, 1);
    mean_from_rowsum<<<1, 256>>>(p_mean_t, 1, 1.f / NT);
    cov_epilogue_kernel<<<dim3(CDIM, 1), 256>>>(p_part, 1, p_mean_t, p_cov_t, 1.f / NT);
    frob_kernel<<<1, 256>>>(p_cov_t, p_norm_t);
    ns_init_kernel<<<dim3(1, 64), 256>>>(p_cov_t, p_norm_t, p_y0, p_z0);
    ns_chain_ffma<<<32, 256>>>(1);
    scale_kernel<<<256, 256>>>(p_y0, p_norm_t, p_S);      // S = cov_t_sqrt

    // ---- x branch: batched cov ----
    syrk_mma_kernel<<<dim3(3, B, NSPLIT), 256, SYRK_SMEM_BYTES>>>(x, p_part, HW, HW / NSPLIT, B);
    mean_from_rowsum<<<B, 256>>>(p_mean_x, B, 1.f / HW);
    cov_epilogue_kernel<<<dim3(CDIM, B), 256>>>(p_part, B, p_mean_x, p_cov_x, 1.f / HW);

    // M = S @ cov @ S  (fp32 FFMA)
    mm256_kernel<<<dim3(16, B), 256>>>(p_S, 0, p_cov_x, MSIZE, p_tmpM, 1.f, 0.f);
    mm256_kernel<<<dim3(16, B), 256>>>(p_tmpM, MSIZE, p_S, 0, p_M, 1.f, 0.f);

    // batched NS sqrt of M (persistent fp32 chain)
    frob_kernel<<<B, 256>>>(p_M, p_norm_b);
    ns_init_kernel<<<dim3(B, 64), 256>>>(p_M, p_norm_b, p_y0, p_z0);
    ns_chain_ffma<<<128, 256>>>(B);

    final_kernel<<<1, 256>>>(p_mean_x, p_mean_t, p_cov_t, p_cov_x,
                             p_y0, p_norm_b, B, (float*)d_out);
}

// round 13
// speedup vs baseline: 1.4223x; 1.4223x over previous
#include <cuda_runtime.h>
#include <cuda_bf16.h>
#include <cstdint>
#include <math.h>

#define CDIM 256
#define BMAX 8
#define NSPLIT 32
#define MSIZE (CDIM*CDIM)

// ---------------- device scratch (no allocations allowed) ----------------
__device__ float g_mean_t[CDIM];
__device__ float g_mean_x[BMAX*CDIM];
__device__ float g_part[NSPLIT*BMAX*MSIZE];     // x-branch split-K partials (64 MB)
__device__ float g_part_t[NSPLIT*MSIZE];        // target-branch partials (8 MB)
__device__ float g_rowsum[NSPLIT*BMAX*CDIM];
__device__ float g_rowsum_t[NSPLIT*CDIM];
__device__ float g_cov_t[MSIZE];
__device__ float g_cov_x[BMAX*MSIZE];
__device__ float g_S[MSIZE];                     // cov_t_sqrt
__device__ float g_tmpM[BMAX*MSIZE];
__device__ float g_M[BMAX*MSIZE];
__device__ float g_y0[BMAX*MSIZE];
__device__ float g_y1[BMAX*MSIZE];
__device__ float g_z0[BMAX*MSIZE];
__device__ float g_z1[BMAX*MSIZE];
__device__ float g_t[BMAX*MSIZE];
__device__ float g_norm_t[1];
__device__ float g_norm_b[BMAX];

// ---------- stream/event for graph fork (created once, before checkpoints) ---
struct ForkRes {
    cudaStream_t s2;
    cudaEvent_t eA, eB;
    ForkRes() {
        cudaStreamCreateWithFlags(&s2, cudaStreamNonBlocking);
        cudaEventCreateWithFlags(&eA, cudaEventDisableTiming);
        cudaEventCreateWithFlags(&eB, cudaEventDisableTiming);
    }
};
static ForkRes g_fork;

// ================= mma helpers (baseline PTX only) =================
__device__ __forceinline__ void mma_bf16(float* d, const uint32_t* a, const uint32_t* b) {
    asm volatile("mma.sync.aligned.m16n8k16.row.col.f32.bf16.bf16.f32 "
        "{%0,%1,%2,%3}, {%4,%5,%6,%7}, {%8,%9}, {%0,%1,%2,%3};"
        : "+f"(d[0]), "+f"(d[1]), "+f"(d[2]), "+f"(d[3])
        : "r"(a[0]), "r"(a[1]), "r"(a[2]), "r"(a[3]), "r"(b[0]), "r"(b[1]));
}
__device__ __forceinline__ void ldsm_x4(uint32_t addr, uint32_t* r) {
    asm volatile("ldmatrix.sync.aligned.m8n8.x4.shared.b16 {%0,%1,%2,%3}, [%4];"
        : "=r"(r[0]), "=r"(r[1]), "=r"(r[2]), "=r"(r[3]) : "r"(addr));
}
__device__ __forceinline__ void ldsm_x2(uint32_t addr, uint32_t* r) {
    asm volatile("ldmatrix.sync.aligned.m8n8.x2.shared.b16 {%0,%1}, [%2];"
        : "=r"(r[0]), "=r"(r[1]) : "r"(addr));
}
__device__ __forceinline__ uint32_t smem_to_u32(const void* smem_ptr) {
    uint32_t addr;
    asm("{ .reg .u64 tmp; cvta.to.shared.u64 tmp, %1; cvt.u32.u64 %0, tmp; }"
        : "=r"(addr) : "l"(smem_ptr));
    return addr;
}
__device__ __forceinline__ uint32_t bits2(__nv_bfloat162 v) {
    return *reinterpret_cast<uint32_t*>(&v);
}

// ================= bf16x3 mma.sync SYRK (R4-validated) + fused row sums ======
#define SYRK_STAGE_BYTES 40960
#define SYRK_SMEM_BYTES  81920

__global__ void __launch_bounds__(256) syrk_mma_kernel(const float* __restrict__ X,
                                                       float* __restrict__ part,
                                                       float* __restrict__ rowsum,
                                                       int K, int klen, int nb)
{
    extern __shared__ char smem[];
    const int t    = threadIdx.x;
    const int lane = t & 31;
    const int wid  = t >> 5;
    const int warp_m = wid & 3;
    const int warp_n = wid >> 2;

    const int t3 = blockIdx.x;
    const int ti = (t3 == 2) ? 1 : 0;
    const int tj = (t3 == 0) ? 0 : 1;
    const bool diag = (ti == tj);
    const int b  = blockIdx.y;
    const int sp = blockIdx.z;

    const uint32_t sbase = smem_to_u32(smem);

    const size_t baseA = (size_t)b * CDIM * K + (size_t)(ti * 128) * K + (size_t)sp * klen;
    const size_t baseB = (size_t)b * CDIM * K + (size_t)(tj * 128) * K + (size_t)sp * klen;
    const int lrow = t >> 3;
    const int lc4  = t & 7;
    const float* gA = X + baseA + (size_t)lrow * K + lc4 * 4;
    const float* gB = X + baseB + (size_t)lrow * K + lc4 * 4;

    const int a_lr = lane & 7, a_lg = lane >> 3;
    const uint32_t a_off = (uint32_t)((a_lr + (a_lg & 1) * 8) * 80 + ((a_lg >> 1) * 8) * 2);
    const uint32_t b_off = (uint32_t)((lane & 7) * 80 + (((lane >> 3) & 1) * 8) * 2);

    float acc[2][8][4] = {};
    float rs[4] = {0.f, 0.f, 0.f, 0.f};
    float4 pa[4], pb[4];
    const int S = klen >> 5;

    #pragma unroll
    for (int it = 0; it < 4; it++) pa[it] = *(const float4*)(gA + (size_t)(it * 32) * K);
    if (!diag) {
        #pragma unroll
        for (int it = 0; it < 4; it++) pb[it] = *(const float4*)(gB + (size_t)(it * 32) * K);
    }

    for (int s = 0; s < S; s++) {
        const uint32_t bufo = (uint32_t)((s & 1) * SYRK_STAGE_BYTES);
        char* bufc = smem + bufo;

        #pragma unroll
        for (int it = 0; it < 4; it++) {
            float4 v = pa[it];
            if (diag) rs[it] += (v.x + v.y) + (v.z + v.w);
            __nv_bfloat162 h01 = __floats2bfloat162_rn(v.x, v.y);
            __nv_bfloat162 h23 = __floats2bfloat162_rn(v.z, v.w);
            float l0 = v.x - __low2float(h01);
            float l1 = v.y - __high2float(h01);
            float l2 = v.z - __low2float(h23);
            float l3 = v.w - __high2float(h23);
            __nv_bfloat162 lo01 = __floats2bfloat162_rn(l0, l1);
            __nv_bfloat162 lo23 = __floats2bfloat162_rn(l2, l3);
            uint32_t off = (uint32_t)((lrow + it * 32) * 80 + lc4 * 8);
            *(uint2*)(bufc + off)         = make_uint2(bits2(h01), bits2(h23));
            *(uint2*)(bufc + 10240 + off) = make_uint2(bits2(lo01), bits2(lo23));
        }
        if (!diag) {
            #pragma unroll
            for (int it = 0; it < 4; it++) {
                float4 v = pb[it];
                __nv_bfloat162 h01 = __floats2bfloat162_rn(v.x, v.y);
                __nv_bfloat162 h23 = __floats2bfloat162_rn(v.z, v.w);
                float l0 = v.x - __low2float(h01);
                float l1 = v.y - __high2float(h01);
                float l2 = v.z - __low2float(h23);
                float l3 = v.w - __high2float(h23);
                __nv_bfloat162 lo01 = __floats2bfloat162_rn(l0, l1);
                __nv_bfloat162 lo23 = __floats2bfloat162_rn(l2, l3);
                uint32_t off = (uint32_t)((lrow + it * 32) * 80 + lc4 * 8);
                *(uint2*)(bufc + 20480 + off) = make_uint2(bits2(h01), bits2(h23));
                *(uint2*)(bufc + 30720 + off) = make_uint2(bits2(lo01), bits2(lo23));
            }
        }
        __syncthreads();

        if (s + 1 < S) {
            const float* nA = gA + (s + 1) * 32;
            #pragma unroll
            for (int it = 0; it < 4; it++) pa[it] = *(const float4*)(nA + (size_t)(it * 32) * K);
            if (!diag) {
                const float* nB = gB + (s + 1) * 32;
                #pragma unroll
                for (int it = 0; it < 4; it++) pb[it] = *(const float4*)(nB + (size_t)(it * 32) * K);
            }
        }

        const uint32_t ah_base = sbase + bufo;
        const uint32_t al_base = ah_base + 10240;
        const uint32_t bh_base = diag ? ah_base : ah_base + 20480;
        const uint32_t bl_base = diag ? al_base : ah_base + 30720;
        #pragma unroll
        for (int kf = 0; kf < 2; kf++) {
            const uint32_t koff = (uint32_t)(kf * 32);
            uint32_t ah[2][4], al[2][4];
            #pragma unroll
            for (int m = 0; m < 2; m++) {
                uint32_t ro = (uint32_t)((warp_m * 32 + m * 16) * 80) + a_off + koff;
                ldsm_x4(ah_base + ro, ah[m]);
                ldsm_x4(al_base + ro, al[m]);
            }
            #pragma unroll
            for (int n = 0; n < 8; n++) {
                uint32_t ro = (uint32_t)((warp_n * 64 + n * 8) * 80) + b_off + koff;
                uint32_t bh[2], bl[2];
                ldsm_x2(bh_base + ro, bh);
                ldsm_x2(bl_base + ro, bl);
                #pragma unroll
                for (int m = 0; m < 2; m++) {
                    mma_bf16(acc[m][n], ah[m], bh);
                    mma_bf16(acc[m][n], ah[m], bl);
                    mma_bf16(acc[m][n], al[m], bh);
                }
            }
        }
        __syncthreads();
    }

    if (diag) {
        #pragma unroll
        for (int it = 0; it < 4; it++) {
            float r = rs[it];
            r += __shfl_xor_sync(0xffffffffu, r, 1);
            r += __shfl_xor_sync(0xffffffffu, r, 2);
            r += __shfl_xor_sync(0xffffffffu, r, 4);
            if ((t & 7) == 0) {
                int row = ti * 128 + lrow + it * 32;
                rowsum[((size_t)sp * nb + b) * CDIM + row] = r;
            }
        }
    }

    float* osm = (float*)smem;
    {
        int r0 = warp_m * 32 + (lane >> 2);
        int c0 = warp_n * 64 + (lane & 3) * 2;
        #pragma unroll
        for (int m = 0; m < 2; m++) {
            #pragma unroll
            for (int n = 0; n < 8; n++) {
                int rr = r0 + m * 16;
                int cc = c0 + n * 8;
                osm[rr * 128 + cc]           = acc[m][n][0];
                osm[rr * 128 + cc + 1]       = acc[m][n][1];
                osm[(rr + 8) * 128 + cc]     = acc[m][n][2];
                osm[(rr + 8) * 128 + cc + 1] = acc[m][n][3];
            }
        }
    }
    __syncthreads();
    {
        float* out = part + ((size_t)sp * nb + b) * MSIZE
                     + (size_t)(ti * 128) * CDIM + tj * 128;
        #pragma unroll
        for (int it = 0; it < 16; it++) {
            int idx = it * 256 + t;
            int row = idx >> 5;
            int c4  = idx & 31;
            *(float4*)(out + (size_t)row * CDIM + c4 * 4) =
                *(float4*)(osm + row * 128 + c4 * 4);
        }
    }
}

// ---------------- mean from rowsum partials ----------------
__global__ void mean_from_rowsum(float* __restrict__ mean, const float* __restrict__ rowsum,
                                 int nb, float inv_len)
{
    int b = blockIdx.x;
    int c = threadIdx.x;
    float s = 0.f;
    #pragma unroll 8
    for (int sp = 0; sp < NSPLIT; sp++)
        s += rowsum[((size_t)sp * nb + b) * CDIM + c];
    mean[b * CDIM + c] = s * inv_len;
}

// ---------------- cov epilogue ----------------
__global__ void cov_epilogue_kernel(const float* __restrict__ part, int nb,
                                    const float* __restrict__ mean,
                                    float* __restrict__ cov, float inv_n)
{
    int i = blockIdx.x;
    int b = blockIdx.y;
    int j = threadIdx.x;
    int ii = min(i, j), jj = max(i, j);
    float s = 0.f;
    #pragma unroll 8
    for (int sp = 0; sp < NSPLIT; sp++)
        s += part[((size_t)sp * nb + b) * MSIZE + ii * CDIM + jj];
    float v = s * inv_n - mean[b * CDIM + i] * mean[b * CDIM + j] + ((i == j) ? 1e-4f : 0.f);
    cov[(size_t)b * MSIZE + i * CDIM + j] = v;
}

// ---------------- Frobenius norm per matrix ----------------
__global__ void frob_kernel(const float* __restrict__ A, float* __restrict__ norm)
{
    __shared__ float sm[256];
    const float4* p = (const float4*)(A + (size_t)blockIdx.x * MSIZE);
    float s = 0.f;
    for (int i = threadIdx.x; i < MSIZE / 4; i += 256) {
        float4 v = p[i];
        s += v.x * v.x + v.y * v.y + v.z * v.z + v.w * v.w;
    }
    sm[threadIdx.x] = s;
    __syncthreads();
    for (int off = 128; off > 0; off >>= 1) {
        if (threadIdx.x < off) sm[threadIdx.x] += sm[threadIdx.x + off];
        __syncthreads();
    }
    if (threadIdx.x == 0) norm[blockIdx.x] = sqrtf(sm[0]);
}

// ---------------- NS init: y = A/norm (fp32) ----------------
__global__ void ns_init_kernel(const float* __restrict__ A, const float* __restrict__ norm,
                               float* __restrict__ y)
{
    int b = blockIdx.x;
    int i4 = blockIdx.y * 256 + threadIdx.x;
    float inv = 1.f / norm[b];
    size_t off = (size_t)b * MSIZE + (size_t)i4 * 4;
    float4 v = *(const float4*)(A + off);
    v.x *= inv; v.y *= inv; v.z *= inv; v.w *= inv;
    *(float4*)(y + off) = v;
}

// ---------------- iter0 z: z1 = 1.5 I - 0.5 y0 (elementwise) ----------------
__global__ void zinit_iter0_kernel(const float* __restrict__ y0, float* __restrict__ z1)
{
    int b = blockIdx.x;
    int i4 = blockIdx.y * 256 + threadIdx.x;
    size_t off = (size_t)b * MSIZE + (size_t)i4 * 4;
    float4 v = *(const float4*)(y0 + off);
    int e = i4 * 4;
    int row = e >> 8;
    int c0 = e & 255;
    float4 o;
    o.x = ((row == c0    ) ? 1.5f : 0.f) - 0.5f * v.x;
    o.y = ((row == c0 + 1) ? 1.5f : 0.f) - 0.5f * v.y;
    o.z = ((row == c0 + 2) ? 1.5f : 0.f) - 0.5f * v.z;
    o.w = ((row == c0 + 3) ? 1.5f : 0.f) - 0.5f * v.w;
    *(float4*)(z1 + off) = o;
}

// ===== fp32 FFMA 64x64 tile, register-prefetch double-buffered ==============
// C = alpha*(A@B) + beta*I + gamma*Gm   (Gm nullable)
__device__ __forceinline__ void ffma_tile(
    const float* __restrict__ A, const float* __restrict__ B, float* __restrict__ C,
    const float* __restrict__ Gm,
    int ti, int tj, float alpha, float beta, float gamma,
    float (*As)[68], float (*Bs)[68])
{
    const int t  = threadIdx.x;
    const int lr = t >> 2;
    const int lk = (t & 3) * 4;
    const int br = t >> 4;
    const int bc = (t & 15) * 4;
    const int ty = t >> 4;
    const int tx = t & 15;

    float acc[4][4] = {};

    const float* pA = A + (size_t)(ti * 64 + lr) * CDIM + lk;
    const float* pB = B + (size_t)br * CDIM + tj * 64 + bc;
    float4 va = *(const float4*)pA;
    float4 vb = *(const float4*)pB;

    for (int k0 = 0; k0 < CDIM; k0 += 16) {
        __syncthreads();
        As[lk+0][lr] = va.x; As[lk+1][lr] = va.y; As[lk+2][lr] = va.z; As[lk+3][lr] = va.w;
        *(float4*)&Bs[br][bc] = vb;
        __syncthreads();
        if (k0 + 16 < CDIM) {
            va = *(const float4*)(pA + k0 + 16);
            vb = *(const float4*)(pB + (size_t)(k0 + 16) * CDIM);
        }
        #pragma unroll
        for (int k = 0; k < 16; k++) {
            float4 a4 = *(const float4*)&As[k][ty * 4];
            float4 b4 = *(const float4*)&Bs[k][tx * 4];
            acc[0][0] += a4.x * b4.x; acc[0][1] += a4.x * b4.y; acc[0][2] += a4.x * b4.z; acc[0][3] += a4.x * b4.w;
            acc[1][0] += a4.y * b4.x; acc[1][1] += a4.y * b4.y; acc[1][2] += a4.y * b4.z; acc[1][3] += a4.y * b4.w;
            acc[2][0] += a4.z * b4.x; acc[2][1] += a4.z * b4.y; acc[2][2] += a4.z * b4.z; acc[2][3] += a4.z * b4.w;
            acc[3][0] += a4.w * b4.x; acc[3][1] += a4.w * b4.y; acc[3][2] += a4.w * b4.z; acc[3][3] += a4.w * b4.w;
        }
    }

    #pragma unroll
    for (int i = 0; i < 4; i++) {
        int gi = ti * 64 + ty * 4 + i;
        #pragma unroll
        for (int j = 0; j < 4; j++) {
            int gj = tj * 64 + tx * 4 + j;
            float v = alpha * acc[i][j] + ((gi == gj) ? beta : 0.f);
            if (Gm) v += gamma * Gm[gi * CDIM + gj];
            C[gi * CDIM + gj] = v;
        }
    }
}

// dual-set batched matmul (two operand sets share a launch)
__global__ void __launch_bounds__(256) mm256_kernel(
    const float* __restrict__ A1, int sA1, const float* __restrict__ B1, int sB1, float* __restrict__ C1,
    const float* __restrict__ A2, int sA2, const float* __restrict__ B2, int sB2, float* __restrict__ C2,
    int nb1, float alpha, float beta)
{
    __shared__ float As[16][68];
    __shared__ float Bs[16][68];
    int item = blockIdx.y;
    const float* A; const float* B; float* Cc;
    if (item < nb1) {
        A  = A1 + (size_t)sA1 * item;
        B  = B1 + (size_t)sB1 * item;
        Cc = C1 + (size_t)item * MSIZE;
    } else {
        int i2 = item - nb1;
        A  = A2 + (size_t)sA2 * i2;
        B  = B2 + (size_t)sB2 * i2;
        Cc = C2 + (size_t)i2 * MSIZE;
    }
    ffma_tile(A, B, Cc, nullptr, blockIdx.x >> 2, blockIdx.x & 3, alpha, beta, 0.f, As, Bs);
}

// iter0: C = alpha*(A@A) + gamma*A
__global__ void __launch_bounds__(256) mm256_iter0_kernel(
    const float* __restrict__ A, float* __restrict__ C, float alpha, float gamma)
{
    __shared__ float As[16][68];
    __shared__ float Bs[16][68];
    const int item = blockIdx.y;
    const float* Ab = A + (size_t)item * MSIZE;
    ffma_tile(Ab, Ab, C + (size_t)item * MSIZE, Ab,
              blockIdx.x >> 2, blockIdx.x & 3, alpha, 0.f, gamma, As, Bs);
}

// ---------------- S = y * sqrt(norm_t) ----------------
__global__ void scale_kernel(const float* __restrict__ y, const float* __restrict__ norm,
                             float* __restrict__ out)
{
    float sc = sqrtf(norm[0]);
    int i = blockIdx.x * 256 + threadIdx.x;
    out[i] = y[i] * sc;
}

// ---------------- final: mean_diff + cov_diff ----------------
__global__ void final_kernel(const float* __restrict__ mean_x, const float* __restrict__ mean_t,
                             const float* __restrict__ cov_t, const float* __restrict__ cov_x,
                             const float* __restrict__ yb, const float* __restrict__ normb,
                             int B, float* __restrict__ out)
{
    __shared__ float sm[256];
    float s = 0.f;
    int n = B * CDIM;
    for (int idx = threadIdx.x; idx < n; idx += 256) {
        int b = idx >> 8;
        int c = idx & 255;
        float d = mean_x[idx] - mean_t[c];
        float st = sqrtf(normb[b]) * yb[(size_t)b * MSIZE + c * (CDIM + 1)];
        s += d * d + cov_t[c * (CDIM + 1)] + cov_x[(size_t)b * MSIZE + c * (CDIM + 1)] - 2.f * st;
    }
    sm[threadIdx.x] = s;
    __syncthreads();
    for (int off = 128; off > 0; off >>= 1) {
        if (threadIdx.x < off) sm[threadIdx.x] += sm[threadIdx.x + off];
        __syncthreads();
    }
    if (threadIdx.x == 0) out[0] = sm[0] / (float)n;
}

// ---------------- host orchestration ----------------
template <typename T>
static float* sym_addr(const T& symbol)
{
    void* p = nullptr;
    cudaGetSymbolAddress(&p, symbol);
    return (float*)p;
}

// full NS chain on a stream: y0 holds normalized input; result lands in y0
static void run_ns_chain(int nb, cudaStream_t st,
                         float* y0, float* y1, float* z0, float* z1, float* tb)
{
    float* yb[2] = {y0, y1};
    float* zb[2] = {z0, z1};
    // iter0: y1 = -0.5*(y0@y0) + 1.5*y0 ; z1 = 1.5I - 0.5*y0
    mm256_iter0_kernel<<<dim3(16, nb), 256, 0, st>>>(y0, y1, -0.5f, 1.5f);
    zinit_iter0_kernel<<<dim3(nb, 64), 256, 0, st>>>(y0, z1);
    int cur = 1;
    // iters 1..10
    for (int it = 1; it <= 10; it++) {
        mm256_kernel<<<dim3(16, nb), 256, 0, st>>>(zb[cur], MSIZE, yb[cur], MSIZE, tb,
                                                   nullptr, 0, nullptr, 0, nullptr,
                                                   nb, -0.5f, 1.5f);
        mm256_kernel<<<dim3(16, 2 * nb), 256, 0, st>>>(yb[cur], MSIZE, tb, MSIZE, yb[cur ^ 1],
                                                       tb, MSIZE, zb[cur], MSIZE, zb[cur ^ 1],
                                                       nb, 1.f, 0.f);
        cur ^= 1;
    }
    // iter11: t, then y only (z never used again)
    mm256_kernel<<<dim3(16, nb), 256, 0, st>>>(zb[cur], MSIZE, yb[cur], MSIZE, tb,
                                               nullptr, 0, nullptr, 0, nullptr,
                                               nb, -0.5f, 1.5f);
    mm256_kernel<<<dim3(16, nb), 256, 0, st>>>(yb[cur], MSIZE, tb, MSIZE, yb[cur ^ 1],
                                               nullptr, 0, nullptr, 0, nullptr,
                                               nb, 1.f, 0.f);
    // cur started at 1, toggled 10 times -> 1; final y in yb[0] = y0
}

extern "C" void kernel_launch(void* const* d_in, const int* in_sizes, int n_in,
                              void* d_out, int out_size)
{
    const float* x  = (const float*)d_in[0];
    const float* tf = (const float*)d_in[1];
    const int HW = 65536;
    int B  = in_sizes[0] / (CDIM * HW);         // 8
    int NT = in_sizes[1] / CDIM;                // 16384

    float* p_mean_t   = sym_addr(g_mean_t);
    float* p_mean_x   = sym_addr(g_mean_x);
    float* p_part     = sym_addr(g_part);
    float* p_part_t   = sym_addr(g_part_t);
    float* p_rowsum   = sym_addr(g_rowsum);
    float* p_rowsum_t = sym_addr(g_rowsum_t);
    float* p_cov_t    = sym_addr(g_cov_t);
    float* p_cov_x    = sym_addr(g_cov_x);
    float* p_S        = sym_addr(g_S);
    float* p_tmpM     = sym_addr(g_tmpM);
    float* p_M        = sym_addr(g_M);
    float* p_y0       = sym_addr(g_y0);
    float* p_y1       = sym_addr(g_y1);
    float* p_z0       = sym_addr(g_z0);
    float* p_z1       = sym_addr(g_z1);
    float* p_t        = sym_addr(g_t);
    float* p_norm_t   = sym_addr(g_norm_t);
    float* p_norm_b   = sym_addr(g_norm_b);

    cudaFuncSetAttribute(syrk_mma_kernel, cudaFuncAttributeMaxDynamicSharedMemorySize,
                         SYRK_SMEM_BYTES);

    cudaStream_t s2 = g_fork.s2;

    // ---- fork: target branch on s2 ----
    cudaEventRecord(g_fork.eA, 0);
    cudaStreamWaitEvent(s2, g_fork.eA, 0);

    syrk_mma_kernel<<<dim3(3, 1, NSPLIT), 256, SYRK_SMEM_BYTES, s2>>>(
        tf, p_part_t, p_rowsum_t, NT, NT / NSPLIT, 1);
    mean_from_rowsum<<<1, 256, 0, s2>>>(p_mean_t, p_rowsum_t, 1, 1.f / NT);
    cov_epilogue_kernel<<<dim3(CDIM, 1), 256, 0, s2>>>(p_part_t, 1, p_mean_t, p_cov_t, 1.f / NT);
    frob_kernel<<<1, 256, 0, s2>>>(p_cov_t, p_norm_t);
    ns_init_kernel<<<dim3(1, 64), 256, 0, s2>>>(p_cov_t, p_norm_t, p_y0);
    run_ns_chain(1, s2, p_y0, p_y1, p_z0, p_z1, p_t);
    scale_kernel<<<256, 256, 0, s2>>>(p_y0, p_norm_t, p_S);   // S = cov_t_sqrt
    cudaEventRecord(g_fork.eB, s2);

    // ---- main stream: x branch (concurrent with target branch) ----
    syrk_mma_kernel<<<dim3(3, B, NSPLIT), 256, SYRK_SMEM_BYTES>>>(
        x, p_part, p_rowsum, HW, HW / NSPLIT, B);
    mean_from_rowsum<<<B, 256>>>(p_mean_x, p_rowsum, B, 1.f / HW);
    cov_epilogue_kernel<<<dim3(CDIM, B), 256>>>(p_part, B, p_mean_x, p_cov_x, 1.f / HW);

    // ---- join, then sandwich + batched NS ----
    cudaStreamWaitEvent(0, g_fork.eB, 0);
    mm256_kernel<<<dim3(16, B), 256>>>(p_S, 0, p_cov_x, MSIZE, p_tmpM,
                                       nullptr, 0, nullptr, 0, nullptr, B, 1.f, 0.f);
    mm256_kernel<<<dim3(16, B), 256>>>(p_tmpM, MSIZE, p_S, 0, p_M,
                                       nullptr, 0, nullptr, 0, nullptr, B, 1.f, 0.f);

    frob_kernel<<<B, 256>>>(p_M, p_norm_b);
    ns_init_kernel<<<dim3(B, 64), 256>>>(p_M, p_norm_b, p_y0);
    run_ns_chain(B, 0, p_y0, p_y1, p_z0, p_z1, p_t);

    final_kernel<<<1, 256>>>(p_mean_x, p_mean_t, p_cov_t, p_cov_x,
                             p_y0, p_norm_b, B, (float*)d_out);
}